// round 1
// baseline (speedup 1.0000x reference)
#include <cuda_runtime.h>

// MovementEmbeddingModule: bs=4, d=16, K=10, C=3, h=w=128
// out: (bs, K*6, d, h, w) float32
//   channel j within each k: 0=heatmap, 1..2=kp_video_diff (const planes), 3..5=deformed RGB

#define WIDTH  128
#define HEIGHT 128
#define KNUM   10
#define DNUM   16
#define CNUM   3
#define BSNUM  4

__global__ __launch_bounds__(256, 8) void movement_kernel(
    const float* __restrict__ kp_app,   // (4,1,10,2)
    const float* __restrict__ kp_vid,   // (4,16,10,2)
    const float* __restrict__ img,      // (4,3,1,128,128)
    float* __restrict__ out)            // (4,60,16,128,128)
{
    const int bdk = blockIdx.x;                // 0..639
    const int k   = bdk % KNUM;
    const int t   = bdk / KNUM;
    const int dd  = t % DNUM;
    const int b   = t / DNUM;

    // keypoints (broadcast loads)
    const float2 kva = *(const float2*)(kp_app + (b * KNUM + k) * 2);
    const float2 kv  = *(const float2*)(kp_vid + ((b * DNUM + dd) * KNUM + k) * 2);
    const float2 kv0 = *(const float2*)(kp_vid + ((b * DNUM + 0)  * KNUM + k) * 2);

    const float diffx = kv.x - kv0.x;
    const float diffy = kv.y - kv0.y;
    const float mx = diffx + kva.x;            // kp_mean for this (b,dd,k)
    const float my = diffy + kva.y;
    const float vdx = -diffx;                  // kp_video_diff (also deformation offset)
    const float vdy = -diffy;

    const int x = threadIdx.x;                 // 0..127
    const float gx = -1.0f + (float)x * (2.0f / 127.0f);

    // x-dependent heatmap pieces (constant over y loop)
    const float dxm = gx - mx;
    const float hx_d = -50.0f * dxm * dxm;
    const float dxa = gx - kva.x;
    const float hx_0 = -50.0f * dxa * dxa;

    // x part of the bilinear sample (constant over y loop)
    const float xi  = (gx + vdx + 1.0f) * 63.5f;
    const float x0f = floorf(xi);
    const float wx1 = xi - x0f;
    const float wx0 = 1.0f - wx1;
    const int   ix0 = (int)x0f;
    const int   ix1 = ix0 + 1;
    const bool  vx0 = (ix0 >= 0) && (ix0 <= WIDTH - 1);
    const bool  vx1 = (ix1 >= 0) && (ix1 <= WIDTH - 1);
    const int   cx0 = min(max(ix0, 0), WIDTH - 1);
    const int   cx1 = min(max(ix1, 0), WIDTH - 1);

    const float* imgb = img + (size_t)b * CNUM * HEIGHT * WIDTH;
    const int chStride = DNUM * HEIGHT * WIDTH;
    float* outb = out + ((size_t)(b * (KNUM * 6) + k * 6) * DNUM + dd) * (size_t)(HEIGHT * WIDTH);

    #pragma unroll 2
    for (int it = 0; it < 8; ++it) {
        const int y = blockIdx.y * 16 + it * 2 + threadIdx.y;
        const float gy = -1.0f + (float)y * (2.0f / 127.0f);

        // heatmap = exp(..d..) - exp(..frame0..)
        const float dym = gy - my;
        const float dya = gy - kva.y;
        const float hm = __expf(fmaf(-50.0f, dym * dym, hx_d))
                       - __expf(fmaf(-50.0f, dya * dya, hx_0));

        // y part of bilinear
        const float yi  = (gy + vdy + 1.0f) * 63.5f;
        const float y0f = floorf(yi);
        const float wy1 = yi - y0f;
        const float wy0 = 1.0f - wy1;
        const int   iy0 = (int)y0f;
        const int   iy1 = iy0 + 1;
        const bool  vy0 = (iy0 >= 0) && (iy0 <= HEIGHT - 1);
        const bool  vy1 = (iy1 >= 0) && (iy1 <= HEIGHT - 1);
        const int   cy0 = min(max(iy0, 0), HEIGHT - 1);
        const int   cy1 = min(max(iy1, 0), HEIGHT - 1);

        const float w00 = (vx0 && vy0) ? wx0 * wy0 : 0.0f;
        const float w10 = (vx1 && vy0) ? wx1 * wy0 : 0.0f;
        const float w01 = (vx0 && vy1) ? wx0 * wy1 : 0.0f;
        const float w11 = (vx1 && vy1) ? wx1 * wy1 : 0.0f;

        const int r0 = cy0 * WIDTH;
        const int r1 = cy1 * WIDTH;
        const int o  = y * WIDTH + x;

        outb[o] = hm;
        outb[chStride + o]     = vdx;
        outb[2 * chStride + o] = vdy;

        #pragma unroll
        for (int c = 0; c < CNUM; ++c) {
            const float* ic = imgb + c * (HEIGHT * WIDTH);
            const float c00 = __ldg(ic + r0 + cx0);
            const float c10 = __ldg(ic + r0 + cx1);
            const float c01 = __ldg(ic + r1 + cx0);
            const float c11 = __ldg(ic + r1 + cx1);
            const float v = c00 * w00 + c10 * w10 + c01 * w01 + c11 * w11;
            outb[(3 + c) * chStride + o] = v;
        }
    }
}

extern "C" void kernel_launch(void* const* d_in, const int* in_sizes, int n_in,
                              void* d_out, int out_size) {
    // Robustly pick inputs by element count.
    const float* kp_app = nullptr;   // 80
    const float* kp_vid = nullptr;   // 1280
    const float* img    = nullptr;   // 196608
    for (int i = 0; i < n_in; ++i) {
        if (in_sizes[i] == BSNUM * 1 * KNUM * 2)               kp_app = (const float*)d_in[i];
        else if (in_sizes[i] == BSNUM * DNUM * KNUM * 2)       kp_vid = (const float*)d_in[i];
        else if (in_sizes[i] == BSNUM * CNUM * HEIGHT * WIDTH) img    = (const float*)d_in[i];
    }
    float* out = (float*)d_out;

    dim3 grid(BSNUM * DNUM * KNUM, 8, 1);   // 640 x 8
    dim3 block(128, 2, 1);
    movement_kernel<<<grid, block>>>(kp_app, kp_vid, img, out);
}

// round 2
// speedup vs baseline: 1.0230x; 1.0230x over previous
#include <cuda_runtime.h>
#include <cstdint>

// MovementEmbeddingModule: bs=4, d=16, K=10, C=3, h=w=128
// out: (bs, K*6, d, h, w) float32
// Key insight: the grid-sample step is exactly 1 source pixel per output pixel,
// so bilinear weights are constant per (b,d,k) and it's a shifted 2x2 filter.
// Stores go through smem + cp.async.bulk to avoid STG issue cost.

#define WIDTH  128
#define HEIGHT 128
#define KNUM   10
#define DNUM   16
#define CNUM   3
#define BSNUM  4
#define SLAB   16

__global__ __launch_bounds__(256) void movement_kernel(
    const float* __restrict__ kp_app,   // (4,1,10,2)
    const float* __restrict__ kp_vid,   // (4,16,10,2)
    const float* __restrict__ img,      // (4,3,1,128,128)
    float* __restrict__ out)            // (4,60,16,128,128)
{
    __shared__ float sm[6][SLAB * WIDTH];   // 48 KB

    const int bdk = blockIdx.x;             // 0..639
    const int k   = bdk % KNUM;
    const int t   = bdk / KNUM;
    const int dd  = t % DNUM;
    const int b   = t / DNUM;

    const float2 kva = *(const float2*)(kp_app + (b * KNUM + k) * 2);
    const float2 kv  = *(const float2*)(kp_vid + ((b * DNUM + dd) * KNUM + k) * 2);
    const float2 kv0 = *(const float2*)(kp_vid + ((b * DNUM + 0)  * KNUM + k) * 2);

    const float diffx = kv.x - kv0.x;
    const float diffy = kv.y - kv0.y;
    const float mx = diffx + kva.x;
    const float my = diffy + kva.y;
    const float vdx = -diffx;
    const float vdy = -diffy;

    const int tid = threadIdx.x;
    const int xt  = tid & 31;               // 0..31 -> pixels 4xt..4xt+3
    const int yg  = tid >> 5;               // 0..7  -> 2 rows each
    const int x0  = xt * 4;

    // ---- constant bilinear weights + integer shift (x) ----
    const float xi0 = vdx * 63.5f;          // sample coord of output pixel x=0
    const float fx  = floorf(xi0);
    const float wx1 = xi0 - fx;
    const float wx0 = 1.0f - wx1;
    const int   ixb = (int)fx;

    const int c0 = ixb + x0;
    int cc[5];
    float mw0[4], mw1[4];
    #pragma unroll
    for (int j = 0; j < 5; ++j) cc[j] = min(max(c0 + j, 0), WIDTH - 1);
    #pragma unroll
    for (int i = 0; i < 4; ++i) {
        const int ci0 = c0 + i, ci1 = ci0 + 1;
        mw0[i] = (ci0 >= 0 && ci0 < WIDTH) ? wx0 : 0.0f;
        mw1[i] = (ci1 >= 0 && ci1 < WIDTH) ? wx1 : 0.0f;
    }

    // ---- constant weights + shift (y) ----
    const float yi0 = vdy * 63.5f;
    const float fy  = floorf(yi0);
    const float wy1 = yi0 - fy;
    const float wy0 = 1.0f - wy1;
    const int   iyb = (int)fy;

    // ---- heatmap x-terms ----
    float hxd[4], hx0[4];
    #pragma unroll
    for (int i = 0; i < 4; ++i) {
        const float gx = -1.0f + (float)(x0 + i) * (2.0f / 127.0f);
        const float dm = gx - mx;    hxd[i] = -50.0f * dm * dm;
        const float da = gx - kva.x; hx0[i] = -50.0f * da * da;
    }

    const float* imgb = img + (size_t)b * CNUM * HEIGHT * WIDTH;
    const int ybase = blockIdx.y * SLAB + yg * 2;

    // prime top row (shifted row for output row ybase)
    float top[3][5], bot[3][5];
    {
        const int rt  = iyb + ybase;
        const int rtc = min(max(rt, 0), HEIGHT - 1);
        #pragma unroll
        for (int ch = 0; ch < 3; ++ch) {
            const float* p = imgb + ch * (HEIGHT * WIDTH) + rtc * WIDTH;
            #pragma unroll
            for (int j = 0; j < 5; ++j) top[ch][j] = __ldg(p + cc[j]);
        }
    }

    const float4 vdx4 = make_float4(vdx, vdx, vdx, vdx);
    const float4 vdy4 = make_float4(vdy, vdy, vdy, vdy);

    #pragma unroll
    for (int s = 0; s < 2; ++s) {
        const int y  = ybase + s;
        const int rt = iyb + y;
        const int rb = rt + 1;
        const float wyt = (rt >= 0 && rt < HEIGHT) ? wy0 : 0.0f;
        const float wyb = (rb >= 0 && rb < HEIGHT) ? wy1 : 0.0f;
        const int rbc = min(max(rb, 0), HEIGHT - 1);

        #pragma unroll
        for (int ch = 0; ch < 3; ++ch) {
            const float* p = imgb + ch * (HEIGHT * WIDTH) + rbc * WIDTH;
            #pragma unroll
            for (int j = 0; j < 5; ++j) bot[ch][j] = __ldg(p + cc[j]);
        }

        // heatmap
        const float gy  = -1.0f + (float)y * (2.0f / 127.0f);
        const float dym = gy - my;    const float ad = -50.0f * dym * dym;
        const float dya = gy - kva.y; const float aa = -50.0f * dya * dya;
        float4 hm;
        hm.x = __expf(ad + hxd[0]) - __expf(aa + hx0[0]);
        hm.y = __expf(ad + hxd[1]) - __expf(aa + hx0[1]);
        hm.z = __expf(ad + hxd[2]) - __expf(aa + hx0[2]);
        hm.w = __expf(ad + hxd[3]) - __expf(aa + hx0[3]);

        // deformed channels
        float dv[3][4];
        #pragma unroll
        for (int ch = 0; ch < 3; ++ch) {
            #pragma unroll
            for (int i = 0; i < 4; ++i) {
                const float ht = mw0[i] * top[ch][i] + mw1[i] * top[ch][i + 1];
                const float hb = mw0[i] * bot[ch][i] + mw1[i] * bot[ch][i + 1];
                dv[ch][i] = wyt * ht + wyb * hb;
            }
        }

        const int so = (yg * 2 + s) * WIDTH + x0;
        *(float4*)&sm[0][so] = hm;
        *(float4*)&sm[1][so] = vdx4;
        *(float4*)&sm[2][so] = vdy4;
        *(float4*)&sm[3][so] = make_float4(dv[0][0], dv[0][1], dv[0][2], dv[0][3]);
        *(float4*)&sm[4][so] = make_float4(dv[1][0], dv[1][1], dv[1][2], dv[1][3]);
        *(float4*)&sm[5][so] = make_float4(dv[2][0], dv[2][1], dv[2][2], dv[2][3]);

        // rotate rows
        #pragma unroll
        for (int ch = 0; ch < 3; ++ch)
            #pragma unroll
            for (int j = 0; j < 5; ++j) top[ch][j] = bot[ch][j];
    }

    __syncthreads();

    if (tid == 0) {
        asm volatile("fence.proxy.async.shared::cta;" ::: "memory");
        float* outb = out
            + ((size_t)(b * (KNUM * 6) + k * 6) * DNUM + dd) * (size_t)(HEIGHT * WIDTH)
            + (size_t)blockIdx.y * SLAB * WIDTH;
        const int chStride = DNUM * HEIGHT * WIDTH;
        #pragma unroll
        for (int ch = 0; ch < 6; ++ch) {
            const uint32_t saddr = (uint32_t)__cvta_generic_to_shared(&sm[ch][0]);
            asm volatile(
                "cp.async.bulk.global.shared::cta.bulk_group [%0], [%1], %2;"
                :: "l"(outb + (size_t)ch * chStride), "r"(saddr), "r"(SLAB * WIDTH * 4)
                : "memory");
        }
        asm volatile("cp.async.bulk.commit_group;" ::: "memory");
        asm volatile("cp.async.bulk.wait_group 0;" ::: "memory");
    }
}

extern "C" void kernel_launch(void* const* d_in, const int* in_sizes, int n_in,
                              void* d_out, int out_size) {
    const float* kp_app = nullptr;   // 80
    const float* kp_vid = nullptr;   // 1280
    const float* img    = nullptr;   // 196608
    for (int i = 0; i < n_in; ++i) {
        if (in_sizes[i] == BSNUM * 1 * KNUM * 2)               kp_app = (const float*)d_in[i];
        else if (in_sizes[i] == BSNUM * DNUM * KNUM * 2)       kp_vid = (const float*)d_in[i];
        else if (in_sizes[i] == BSNUM * CNUM * HEIGHT * WIDTH) img    = (const float*)d_in[i];
    }
    float* out = (float*)d_out;

    // allow full shared-memory carveout so 4 CTAs/SM fit (4 x 48KB)
    static bool configured = false;
    if (!configured) {
        cudaFuncSetAttribute(movement_kernel,
                             cudaFuncAttributePreferredSharedMemoryCarveout, 100);
        configured = true;
    }

    dim3 grid(BSNUM * DNUM * KNUM, (HEIGHT / SLAB), 1);   // 640 x 8
    dim3 block(256, 1, 1);
    movement_kernel<<<grid, block>>>(kp_app, kp_vid, img, out);
}

// round 3
// speedup vs baseline: 1.0772x; 1.0529x over previous
#include <cuda_runtime.h>

// MovementEmbeddingModule: bs=4, d=16, K=10, C=3, h=w=128
// out: (bs, K*6, d, h, w) float32
// Constant-step grid sample => per-(b,d,k) constant bilinear weights + integer shift.
// Direct STG.128 stores, factored Gaussian, row-rolling 2x2 filter.

#define WIDTH  128
#define HEIGHT 128
#define KNUM   10
#define DNUM   16
#define CNUM   3
#define BSNUM  4
#define ROWS_PER_WARP 8

__global__ __launch_bounds__(128) void movement_kernel(
    const float* __restrict__ kp_app,   // (4,1,10,2)
    const float* __restrict__ kp_vid,   // (4,16,10,2)
    const float* __restrict__ img,      // (4,3,1,128,128)
    float* __restrict__ out)            // (4,60,16,128,128)
{
    const int bdk = blockIdx.x;             // 0..639
    const int k   = bdk % KNUM;
    const int t   = bdk / KNUM;
    const int dd  = t % DNUM;
    const int b   = t / DNUM;

    const float2 kva = *(const float2*)(kp_app + (b * KNUM + k) * 2);
    const float2 kv  = *(const float2*)(kp_vid + ((b * DNUM + dd) * KNUM + k) * 2);
    const float2 kv0 = *(const float2*)(kp_vid + ((b * DNUM + 0)  * KNUM + k) * 2);

    const float diffx = kv.x - kv0.x;
    const float diffy = kv.y - kv0.y;
    const float mx = diffx + kva.x;
    const float my = diffy + kva.y;
    const float vdx = -diffx;
    const float vdy = -diffy;

    const int lane = threadIdx.x & 31;
    const int warp = threadIdx.x >> 5;      // 0..3
    const int x0   = lane * 4;
    const int ybase = blockIdx.y * (4 * ROWS_PER_WARP) + warp * ROWS_PER_WARP;

    // ---- constant bilinear weights + integer shift (x) ----
    const float xi0 = vdx * 63.5f;
    const float fx  = floorf(xi0);
    const float wx1 = xi0 - fx;
    const float wx0 = 1.0f - wx1;
    const int   ixb = (int)fx;

    const int c0 = ixb + x0;
    int cc[5];
    float mw0[4], mw1[4];
    #pragma unroll
    for (int j = 0; j < 5; ++j) cc[j] = min(max(c0 + j, 0), WIDTH - 1);
    #pragma unroll
    for (int i = 0; i < 4; ++i) {
        const int ci0 = c0 + i, ci1 = ci0 + 1;
        mw0[i] = (ci0 >= 0 && ci0 < WIDTH) ? wx0 : 0.0f;
        mw1[i] = (ci1 >= 0 && ci1 < WIDTH) ? wx1 : 0.0f;
    }

    // ---- constant weights + shift (y) ----
    const float yi0 = vdy * 63.5f;
    const float fy  = floorf(yi0);
    const float wy1 = yi0 - fy;
    const float wy0 = 1.0f - wy1;
    const int   iyb = (int)fy;

    // ---- factored heatmap x-terms: exp once per thread ----
    float exd[4], ex0[4];
    #pragma unroll
    for (int i = 0; i < 4; ++i) {
        const float gx = fmaf((float)(x0 + i), 2.0f / 127.0f, -1.0f);
        const float dm = gx - mx;    exd[i] = __expf(-50.0f * dm * dm);
        const float da = gx - kva.x; ex0[i] = __expf(-50.0f * da * da);
    }

    const float* imgb = img + (size_t)b * CNUM * HEIGHT * WIDTH;
    const int chStride = DNUM * HEIGHT * WIDTH;
    float* outb = out
        + ((size_t)(b * (KNUM * 6) + k * 6) * DNUM + dd) * (size_t)(HEIGHT * WIDTH)
        + x0;

    const float4 vdx4 = make_float4(vdx, vdx, vdx, vdx);
    const float4 vdy4 = make_float4(vdy, vdy, vdy, vdy);

    // prime top row (sample row for output row ybase)
    float top[3][5], bot[3][5];
    {
        const int rt  = iyb + ybase;
        const int rtc = min(max(rt, 0), HEIGHT - 1);
        #pragma unroll
        for (int ch = 0; ch < 3; ++ch) {
            const float* p = imgb + ch * (HEIGHT * WIDTH) + rtc * WIDTH;
            #pragma unroll
            for (int j = 0; j < 5; ++j) top[ch][j] = __ldg(p + cc[j]);
        }
    }

    #pragma unroll 2
    for (int r = 0; r < ROWS_PER_WARP; ++r) {
        const int y  = ybase + r;
        const int rt = iyb + y;
        const int rb = rt + 1;
        const float wyt = (rt >= 0 && rt < HEIGHT) ? wy0 : 0.0f;
        const float wyb = (rb >= 0 && rb < HEIGHT) ? wy1 : 0.0f;
        const int rbc = min(max(rb, 0), HEIGHT - 1);

        #pragma unroll
        for (int ch = 0; ch < 3; ++ch) {
            const float* p = imgb + ch * (HEIGHT * WIDTH) + rbc * WIDTH;
            #pragma unroll
            for (int j = 0; j < 5; ++j) bot[ch][j] = __ldg(p + cc[j]);
        }

        // heatmap: factored Gaussian (2 MUFU per row instead of 8)
        const float gy  = fmaf((float)y, 2.0f / 127.0f, -1.0f);
        const float dym = gy - my;    const float eyd = __expf(-50.0f * dym * dym);
        const float dya = gy - kva.y; const float eya = __expf(-50.0f * dya * dya);
        float4 hm;
        hm.x = eyd * exd[0] - eya * ex0[0];
        hm.y = eyd * exd[1] - eya * ex0[1];
        hm.z = eyd * exd[2] - eya * ex0[2];
        hm.w = eyd * exd[3] - eya * ex0[3];

        // deformed channels (constant-weight 2x2 filter, shared corners)
        float4 dv[3];
        #pragma unroll
        for (int ch = 0; ch < 3; ++ch) {
            float v[4];
            #pragma unroll
            for (int i = 0; i < 4; ++i) {
                const float ht = mw0[i] * top[ch][i] + mw1[i] * top[ch][i + 1];
                const float hb = mw0[i] * bot[ch][i] + mw1[i] * bot[ch][i + 1];
                v[i] = wyt * ht + wyb * hb;
            }
            dv[ch] = make_float4(v[0], v[1], v[2], v[3]);
        }

        float* o = outb + y * WIDTH;
        *(float4*)(o)                = hm;
        *(float4*)(o + chStride)     = vdx4;
        *(float4*)(o + 2 * chStride) = vdy4;
        *(float4*)(o + 3 * chStride) = dv[0];
        *(float4*)(o + 4 * chStride) = dv[1];
        *(float4*)(o + 5 * chStride) = dv[2];

        #pragma unroll
        for (int ch = 0; ch < 3; ++ch)
            #pragma unroll
            for (int j = 0; j < 5; ++j) top[ch][j] = bot[ch][j];
    }
}

extern "C" void kernel_launch(void* const* d_in, const int* in_sizes, int n_in,
                              void* d_out, int out_size) {
    const float* kp_app = nullptr;   // 80
    const float* kp_vid = nullptr;   // 1280
    const float* img    = nullptr;   // 196608
    for (int i = 0; i < n_in; ++i) {
        if (in_sizes[i] == BSNUM * 1 * KNUM * 2)               kp_app = (const float*)d_in[i];
        else if (in_sizes[i] == BSNUM * DNUM * KNUM * 2)       kp_vid = (const float*)d_in[i];
        else if (in_sizes[i] == BSNUM * CNUM * HEIGHT * WIDTH) img    = (const float*)d_in[i];
    }
    float* out = (float*)d_out;

    dim3 grid(BSNUM * DNUM * KNUM, HEIGHT / (4 * ROWS_PER_WARP), 1);   // 640 x 4
    dim3 block(128, 1, 1);
    movement_kernel<<<grid, block>>>(kp_app, kp_vid, img, out);
}